// round 5
// baseline (speedup 1.0000x reference)
#include <cuda_runtime.h>
#include <cuda_bf16.h>

#define MAX_N 100000
#define MAX_E 1600000
#define IN_DIM 256
#define HID 128
#define OUTD 64

// All scratch + staged inputs live in device globals. Atomics touch ONLY these.
__device__ __align__(16) float g_x[(size_t)MAX_N * IN_DIM];
__device__ __align__(16) int   g_src[MAX_E];
__device__ __align__(16) int   g_dst[MAX_E];
__device__ __align__(16) float g_W1[IN_DIM * HID];
__device__ __align__(16) float g_b1[HID];
__device__ __align__(16) float g_W2[HID * OUTD];
__device__ __align__(16) float g_b2[OUTD];
__device__ __align__(16) float g_dinv[MAX_N];
__device__ __align__(16) float g_norm[MAX_E];
__device__ __align__(16) float g_h1[(size_t)MAX_N * HID];
__device__ __align__(16) float g_agg1[(size_t)MAX_N * HID];
__device__ __align__(16) float g_h2[(size_t)MAX_N * OUTD];
__device__ __align__(16) float g_agg2[(size_t)MAX_N * OUTD];
__device__ int g_is_i32;   // 1 if edge_index buffer is int32, 0 if int64

// ---------------------------------------------------------------------------
// Edge-index dtype detection + staging
// ---------------------------------------------------------------------------
// Interpret the first min(E,4096) elements as u64. True int64 indices (< 1e5)
// have zero high words; an int32 buffer packs two indices per u64, so some
// high word is nonzero. All reads stay within bytes [0, 8*4096) — in-bounds
// for BOTH interpretations (int32 buffer is 8E bytes, int64 is 16E bytes).
__global__ void detect_idx_kernel(const void* __restrict__ ei, int E) {
    const unsigned long long* p = (const unsigned long long*)ei;
    __shared__ int found;
    if (threadIdx.x == 0) found = 0;
    __syncthreads();
    int lim = E < 4096 ? E : 4096;
    for (int j = threadIdx.x; j < lim; j += blockDim.x) {
        unsigned long long v = p[j];
        if ((v >> 32) != 0ULL) found = 1;
    }
    __syncthreads();
    if (threadIdx.x == 0) g_is_i32 = found;
}

__global__ void copy_idx_kernel(const void* __restrict__ ei, int E) {
    int e = blockIdx.x * blockDim.x + threadIdx.x;
    if (e >= E) return;
    if (g_is_i32) {
        const int* p = (const int*)ei;
        g_src[e] = p[e];
        g_dst[e] = p[E + e];
    } else {
        const long long* p = (const long long*)ei;
        g_src[e] = (int)p[e];
        g_dst[e] = (int)p[E + e];
    }
}

__global__ void copy_f4_kernel(const float* __restrict__ src, float* __restrict__ dst, int n4) {
    int i = blockIdx.x * blockDim.x + threadIdx.x;
    if (i < n4) reinterpret_cast<float4*>(dst)[i] = reinterpret_cast<const float4*>(src)[i];
}

__global__ void copy_params_kernel(const float* __restrict__ W1, const float* __restrict__ b1,
                                   const float* __restrict__ W2, const float* __restrict__ b2) {
    int i = blockIdx.x * blockDim.x + threadIdx.x;
    if (i < IN_DIM * HID) g_W1[i] = W1[i];
    if (i < HID) g_b1[i] = b1[i];
    if (i < HID * OUTD) g_W2[i] = W2[i];
    if (i < OUTD) g_b2[i] = b2[i];
}

// ---------------------------------------------------------------------------
// Graph-structure kernels (all indices bounds-guarded)
// ---------------------------------------------------------------------------
__global__ void fill_kernel(float* __restrict__ p, int n, float v) {
    int i = blockIdx.x * blockDim.x + threadIdx.x;
    if (i < n) p[i] = v;
}

__global__ void deg_kernel(int E, int n) {
    int e = blockIdx.x * blockDim.x + threadIdx.x;
    if (e < E) {
        unsigned d = (unsigned)g_dst[e];
        if (d < (unsigned)n) atomicAdd(&g_dinv[d], 1.0f);
    }
}

__global__ void dinv_kernel(int n) {
    int i = blockIdx.x * blockDim.x + threadIdx.x;
    if (i < n) g_dinv[i] = rsqrtf(g_dinv[i]);
}

__global__ void norm_kernel(int E, int n) {
    int e = blockIdx.x * blockDim.x + threadIdx.x;
    if (e < E) {
        unsigned s = (unsigned)g_src[e];
        unsigned d = (unsigned)g_dst[e];
        float v = 0.0f;
        if (s < (unsigned)n && d < (unsigned)n) v = g_dinv[s] * g_dinv[d];
        g_norm[e] = v;
    }
}

// out[i][:] = h[i][:] * dinv[i]^2  (self-loop term + accumulator init)
__global__ void init_scaled_kernel(const float* __restrict__ h, float* __restrict__ out,
                                   int n, int dimv) {
    int i = blockIdx.x * blockDim.x + threadIdx.x;
    int total = n * dimv;
    if (i < total) {
        int row = i / dimv;
        float s = g_dinv[row];
        s = s * s;
        float4 v = reinterpret_cast<const float4*>(h)[i];
        v.x *= s; v.y *= s; v.z *= s; v.w *= s;
        reinterpret_cast<float4*>(out)[i] = v;
    }
}

// agg[dst] += h[src] * norm[e]; atomics into __device__ globals ONLY.
__global__ void scatter_kernel(const float* __restrict__ h, float* __restrict__ agg,
                               int E, int n, int dimv) {
    long long idx = (long long)blockIdx.x * blockDim.x + threadIdx.x;
    if (idx >= (long long)E * dimv) return;
    int e = (int)(idx / dimv);
    int c = (int)(idx - (long long)e * dimv);
    unsigned s = (unsigned)g_src[e];
    unsigned d = (unsigned)g_dst[e];
    if (s >= (unsigned)n || d >= (unsigned)n) return;
    float nr = g_norm[e];
    float4 v = reinterpret_cast<const float4*>(h)[(long long)s * dimv + c];
    float* p = agg + ((long long)d * dimv + c) * 4;
    atomicAdd(p + 0, v.x * nr);
    atomicAdd(p + 1, v.y * nr);
    atomicAdd(p + 2, v.z * nr);
    atomicAdd(p + 3, v.w * nr);
}

// a = relu(a + b1), in place on g_agg1
__global__ void relu_bias_kernel(float* __restrict__ a, int n, int dimv) {
    int i = blockIdx.x * blockDim.x + threadIdx.x;
    int total = n * dimv;
    if (i < total) {
        int c = (i % dimv) * 4;
        float4 v = reinterpret_cast<float4*>(a)[i];
        v.x = fmaxf(v.x + g_b1[c + 0], 0.0f);
        v.y = fmaxf(v.y + g_b1[c + 1], 0.0f);
        v.z = fmaxf(v.z + g_b1[c + 2], 0.0f);
        v.w = fmaxf(v.w + g_b1[c + 3], 0.0f);
        reinterpret_cast<float4*>(a)[i] = v;
    }
}

// d_out = agg2 + b2  (single pass, plain coalesced stores into harness buffer)
__global__ void final_store_kernel(float* __restrict__ out, int n, int dimv) {
    int i = blockIdx.x * blockDim.x + threadIdx.x;
    int total = n * dimv;
    if (i < total) {
        int c = (i % dimv) * 4;
        float4 v = reinterpret_cast<const float4*>(g_agg2)[i];
        v.x += g_b2[c + 0];
        v.y += g_b2[c + 1];
        v.z += g_b2[c + 2];
        v.w += g_b2[c + 3];
        reinterpret_cast<float4*>(out)[i] = v;
    }
}

// ---------------------------------------------------------------------------
// smem-tiled fp32 SGEMM: C[M,N] = A[M,K] @ B[K,N]. BM=BN=64, BK=32, 128 thr.
// ---------------------------------------------------------------------------
template <int BM, int BN, int BK, int TM, int TN>
__global__ void sgemm_kernel(int M, int N, int K,
                             const float* __restrict__ A,
                             const float* __restrict__ B,
                             float* __restrict__ C) {
    __shared__ float As[BK][BM + 1];
    __shared__ float Bs[BK][BN];

    const int tid = threadIdx.x;
    const int tcol = tid % (BN / TN);
    const int trow = tid / (BN / TN);
    const int block_row = blockIdx.y * BM;
    const int block_col = blockIdx.x * BN;

    float acc[TM][TN];
#pragma unroll
    for (int m = 0; m < TM; m++)
#pragma unroll
        for (int n = 0; n < TN; n++) acc[m][n] = 0.0f;

    for (int k0 = 0; k0 < K; k0 += BK) {
#pragma unroll
        for (int i = 0; i < 4; i++) {
            int lin = tid + i * 128;
            int r = lin / (BK / 4);
            int kk = (lin % (BK / 4)) * 4;
            float4 v = make_float4(0.f, 0.f, 0.f, 0.f);
            int gr = block_row + r;
            if (gr < M)
                v = *reinterpret_cast<const float4*>(&A[(long long)gr * K + k0 + kk]);
            As[kk + 0][r] = v.x;
            As[kk + 1][r] = v.y;
            As[kk + 2][r] = v.z;
            As[kk + 3][r] = v.w;
        }
#pragma unroll
        for (int i = 0; i < 4; i++) {
            int lin = tid + i * 128;
            int kk = lin / (BN / 4);
            int c = (lin % (BN / 4)) * 4;
            float4 v = *reinterpret_cast<const float4*>(&B[(long long)(k0 + kk) * N + block_col + c]);
            *reinterpret_cast<float4*>(&Bs[kk][c]) = v;
        }
        __syncthreads();

#pragma unroll
        for (int k = 0; k < BK; k++) {
            float a[TM], b[TN];
#pragma unroll
            for (int m = 0; m < TM; m++) a[m] = As[k][trow * TM + m];
#pragma unroll
            for (int n = 0; n < TN; n++) b[n] = Bs[k][tcol * TN + n];
#pragma unroll
            for (int m = 0; m < TM; m++)
#pragma unroll
                for (int n = 0; n < TN; n++) acc[m][n] = fmaf(a[m], b[n], acc[m][n]);
        }
        __syncthreads();
    }

#pragma unroll
    for (int m = 0; m < TM; m++) {
        int gr = block_row + trow * TM + m;
        if (gr < M) {
            float4 v = make_float4(acc[m][0], acc[m][1], acc[m][2], acc[m][3]);
            *reinterpret_cast<float4*>(&C[(long long)gr * N + block_col + tcol * TN]) = v;
        }
    }
}

// ---------------------------------------------------------------------------
// Launch
// ---------------------------------------------------------------------------
extern "C" void kernel_launch(void* const* d_in, const int* in_sizes, int n_in,
                              void* d_out, int out_size) {
    const float* x = (const float*)d_in[0];
    const void* ei = d_in[1];              // int32 or int64 — detected on device
    const float* W1 = (const float*)d_in[2];
    const float* b1 = (const float*)d_in[3];
    const float* W2 = (const float*)d_in[4];
    const float* b2 = (const float*)d_in[5];
    float* out = (float*)d_out;

    const int Nn = in_sizes[0] / IN_DIM;   // 100000
    const int E = in_sizes[1] / 2;         // 1600000
    const int TB = 256;

    float *x_p, *h1_p, *agg1_p, *h2_p, *agg2_p, *W1_p, *W2_p, *dinv_p;
    cudaGetSymbolAddress((void**)&x_p, g_x);
    cudaGetSymbolAddress((void**)&h1_p, g_h1);
    cudaGetSymbolAddress((void**)&agg1_p, g_agg1);
    cudaGetSymbolAddress((void**)&h2_p, g_h2);
    cudaGetSymbolAddress((void**)&agg2_p, g_agg2);
    cudaGetSymbolAddress((void**)&W1_p, g_W1);
    cudaGetSymbolAddress((void**)&W2_p, g_W2);
    cudaGetSymbolAddress((void**)&dinv_p, g_dinv);

    // Stage inputs (dtype-detected edge index; harness buffers read once)
    detect_idx_kernel<<<1, 256>>>(ei, E);
    copy_idx_kernel<<<(E + TB - 1) / TB, TB>>>(ei, E);
    {
        int n4 = Nn * IN_DIM / 4;
        copy_f4_kernel<<<(n4 + TB - 1) / TB, TB>>>(x, x_p, n4);
        copy_params_kernel<<<(IN_DIM * HID + TB - 1) / TB, TB>>>(W1, b1, W2, b2);
    }

    // degree -> dinv -> per-edge norm
    fill_kernel<<<(Nn + TB - 1) / TB, TB>>>(dinv_p, Nn, 1.0f);
    deg_kernel<<<(E + TB - 1) / TB, TB>>>(E, Nn);
    dinv_kernel<<<(Nn + TB - 1) / TB, TB>>>(Nn);
    norm_kernel<<<(E + TB - 1) / TB, TB>>>(E, Nn);

    // Layer 1: h1 = x @ W1 ; agg1 = self + scatter ; relu(+b1)
    {
        dim3 grid(HID / 64, (Nn + 63) / 64);
        sgemm_kernel<64, 64, 32, 8, 4><<<grid, 128>>>(Nn, HID, IN_DIM, x_p, W1_p, h1_p);
        int nv = Nn * (HID / 4);
        init_scaled_kernel<<<(nv + TB - 1) / TB, TB>>>(h1_p, agg1_p, Nn, HID / 4);
        long long work = (long long)E * (HID / 4);
        scatter_kernel<<<(unsigned)((work + TB - 1) / TB), TB>>>(h1_p, agg1_p, E, Nn, HID / 4);
        relu_bias_kernel<<<(nv + TB - 1) / TB, TB>>>(agg1_p, Nn, HID / 4);
    }

    // Layer 2: h2 = agg1 @ W2 ; agg2 = self + scatter ; out = agg2 + b2
    {
        dim3 grid(OUTD / 64, (Nn + 63) / 64);
        sgemm_kernel<64, 64, 32, 8, 4><<<grid, 128>>>(Nn, OUTD, HID, agg1_p, W2_p, h2_p);
        int nv = Nn * (OUTD / 4);
        init_scaled_kernel<<<(nv + TB - 1) / TB, TB>>>(h2_p, agg2_p, Nn, OUTD / 4);
        long long work = (long long)E * (OUTD / 4);
        scatter_kernel<<<(unsigned)((work + TB - 1) / TB), TB>>>(h2_p, agg2_p, E, Nn, OUTD / 4);
        final_store_kernel<<<(nv + TB - 1) / TB, TB>>>(out, Nn, OUTD / 4);
    }
}

// round 6
// speedup vs baseline: 2.6541x; 2.6541x over previous
#include <cuda_runtime.h>
#include <cuda_bf16.h>

#define MAX_N 100000
#define MAX_E 1600000
#define IN_DIM 256
#define HID 128
#define OUTD 64

// Scratch in device globals (allocation-free rule). Atomics touch ONLY these.
__device__ __align__(16) int   g_src[MAX_E];
__device__ __align__(16) int   g_dst[MAX_E];
__device__ __align__(16) int   g_deg[MAX_N];       // edge count per dst
__device__ __align__(16) int   g_rowstart[MAX_N];  // CSR segment base
__device__ __align__(16) int   g_cursor[MAX_N];    // fill cursor
__device__ __align__(16) int2  g_csr[MAX_E];       // (src, __float_as_int(w))
__device__ __align__(16) float g_dinv[MAX_N];
__device__ int g_total;    // running offset for segment bases
__device__ int g_is_i32;   // 1 if edge_index buffer is int32, 0 if int64

// ---------------------------------------------------------------------------
// Edge-index dtype detection + staging (see R3 notes: JAX may emit int32)
// ---------------------------------------------------------------------------
__global__ void detect_idx_kernel(const void* __restrict__ ei, int E) {
    const unsigned long long* p = (const unsigned long long*)ei;
    __shared__ int found;
    if (threadIdx.x == 0) found = 0;
    __syncthreads();
    int lim = E < 4096 ? E : 4096;
    for (int j = threadIdx.x; j < lim; j += blockDim.x) {
        if ((p[j] >> 32) != 0ULL) found = 1;
    }
    __syncthreads();
    if (threadIdx.x == 0) g_is_i32 = found;
}

__global__ void copy_idx_kernel(const void* __restrict__ ei, int E) {
    int e = blockIdx.x * blockDim.x + threadIdx.x;
    if (e >= E) return;
    if (g_is_i32) {
        const int* p = (const int*)ei;
        g_src[e] = p[e];
        g_dst[e] = p[E + e];
    } else {
        const long long* p = (const long long*)ei;
        g_src[e] = (int)p[e];
        g_dst[e] = (int)p[E + e];
    }
}

// ---------------------------------------------------------------------------
// CSR build (by dst)
// ---------------------------------------------------------------------------
__global__ void zero_deg_kernel(int n) {
    int i = blockIdx.x * blockDim.x + threadIdx.x;
    if (i < n) g_deg[i] = 0;
    if (i == 0) g_total = 0;
}

__global__ void count_kernel(int E, int n) {
    int e = blockIdx.x * blockDim.x + threadIdx.x;
    if (e < E) {
        unsigned d = (unsigned)g_dst[e];
        if (d < (unsigned)n) atomicAdd(&g_deg[d], 1);
    }
}

// dinv[i] = rsqrt(deg+1); segment base via fetch-add (ordering irrelevant —
// the gather only needs each dst's edges contiguous).
__global__ void node_setup_kernel(int n) {
    int i = blockIdx.x * blockDim.x + threadIdx.x;
    if (i < n) {
        int d = g_deg[i];
        g_dinv[i] = rsqrtf((float)d + 1.0f);
        int base = atomicAdd(&g_total, d);
        g_rowstart[i] = base;
        g_cursor[i] = base;
    }
}

__global__ void fill_kernel(int E, int n) {
    int e = blockIdx.x * blockDim.x + threadIdx.x;
    if (e >= E) return;
    unsigned s = (unsigned)g_src[e];
    unsigned d = (unsigned)g_dst[e];
    if (s >= (unsigned)n || d >= (unsigned)n) return;
    float w = g_dinv[s] * g_dinv[d];
    int pos = atomicAdd(&g_cursor[d], 1);
    g_csr[pos] = make_int2((int)s, __float_as_int(w));
}

// ---------------------------------------------------------------------------
// Warp-per-node gather aggregation (atomic-free)
// ---------------------------------------------------------------------------
// dim=128: lane owns columns [4*lane, 4*lane+4). acc = h[i]*dinv^2 + sum edges;
// out = relu(acc + b1) -> agg1.
__global__ void gather1_kernel(const float* __restrict__ h,
                               const float* __restrict__ b1,
                               float* __restrict__ aggout, int n) {
    int warp = (int)((blockIdx.x * blockDim.x + threadIdx.x) >> 5);
    int lane = threadIdx.x & 31;
    if (warp >= n) return;
    const float4* hp = (const float4*)h;
    int start = g_rowstart[warp];
    int len = g_deg[warp];
    float di = g_dinv[warp];
    float s2 = di * di;
    float4 acc = hp[(long long)warp * 32 + lane];
    acc.x *= s2; acc.y *= s2; acc.z *= s2; acc.w *= s2;
    const int2* __restrict__ csr = g_csr + start;
    #pragma unroll 2
    for (int j = 0; j < len; j++) {
        int2 ed = csr[j];                        // broadcast load (uniform)
        float w = __int_as_float(ed.y);
        float4 v = hp[(long long)ed.x * 32 + lane];  // coalesced 512B row
        acc.x = fmaf(v.x, w, acc.x);
        acc.y = fmaf(v.y, w, acc.y);
        acc.z = fmaf(v.z, w, acc.z);
        acc.w = fmaf(v.w, w, acc.w);
    }
    float4 bb = ((const float4*)b1)[lane];
    acc.x = fmaxf(acc.x + bb.x, 0.0f);
    acc.y = fmaxf(acc.y + bb.y, 0.0f);
    acc.z = fmaxf(acc.z + bb.z, 0.0f);
    acc.w = fmaxf(acc.w + bb.w, 0.0f);
    ((float4*)aggout)[(long long)warp * 32 + lane] = acc;
}

// dim=64: lane owns columns [2*lane, 2*lane+2). out = acc + b2 -> d_out.
__global__ void gather2_kernel(const float* __restrict__ h,
                               const float* __restrict__ b2,
                               float* __restrict__ out, int n) {
    int warp = (int)((blockIdx.x * blockDim.x + threadIdx.x) >> 5);
    int lane = threadIdx.x & 31;
    if (warp >= n) return;
    const float2* hp = (const float2*)h;
    int start = g_rowstart[warp];
    int len = g_deg[warp];
    float di = g_dinv[warp];
    float s2 = di * di;
    float2 acc = hp[(long long)warp * 32 + lane];
    acc.x *= s2; acc.y *= s2;
    const int2* __restrict__ csr = g_csr + start;
    #pragma unroll 2
    for (int j = 0; j < len; j++) {
        int2 ed = csr[j];
        float w = __int_as_float(ed.y);
        float2 v = hp[(long long)ed.x * 32 + lane];
        acc.x = fmaf(v.x, w, acc.x);
        acc.y = fmaf(v.y, w, acc.y);
    }
    float2 bb = ((const float2*)b2)[lane];
    acc.x += bb.x;
    acc.y += bb.y;
    ((float2*)out)[(long long)warp * 32 + lane] = acc;
}

// ---------------------------------------------------------------------------
// smem-tiled fp32 SGEMM: C[M,N] = A[M,K] @ B[K,N]. BM=BN=64, BK=32, 128 thr.
// ---------------------------------------------------------------------------
template <int BM, int BN, int BK, int TM, int TN>
__global__ void sgemm_kernel(int M, int N, int K,
                             const float* __restrict__ A,
                             const float* __restrict__ B,
                             float* __restrict__ C) {
    __shared__ float As[BK][BM + 1];
    __shared__ float Bs[BK][BN];

    const int tid = threadIdx.x;
    const int tcol = tid % (BN / TN);
    const int trow = tid / (BN / TN);
    const int block_row = blockIdx.y * BM;
    const int block_col = blockIdx.x * BN;

    float acc[TM][TN];
#pragma unroll
    for (int m = 0; m < TM; m++)
#pragma unroll
        for (int n = 0; n < TN; n++) acc[m][n] = 0.0f;

    for (int k0 = 0; k0 < K; k0 += BK) {
#pragma unroll
        for (int i = 0; i < 4; i++) {
            int lin = tid + i * 128;
            int r = lin / (BK / 4);
            int kk = (lin % (BK / 4)) * 4;
            float4 v = make_float4(0.f, 0.f, 0.f, 0.f);
            int gr = block_row + r;
            if (gr < M)
                v = *reinterpret_cast<const float4*>(&A[(long long)gr * K + k0 + kk]);
            As[kk + 0][r] = v.x;
            As[kk + 1][r] = v.y;
            As[kk + 2][r] = v.z;
            As[kk + 3][r] = v.w;
        }
#pragma unroll
        for (int i = 0; i < 4; i++) {
            int lin = tid + i * 128;
            int kk = lin / (BN / 4);
            int c = (lin % (BN / 4)) * 4;
            float4 v = *reinterpret_cast<const float4*>(&B[(long long)(k0 + kk) * N + block_col + c]);
            *reinterpret_cast<float4*>(&Bs[kk][c]) = v;
        }
        __syncthreads();

#pragma unroll
        for (int k = 0; k < BK; k++) {
            float a[TM], b[TN];
#pragma unroll
            for (int m = 0; m < TM; m++) a[m] = As[k][trow * TM + m];
#pragma unroll
            for (int n = 0; n < TN; n++) b[n] = Bs[k][tcol * TN + n];
#pragma unroll
            for (int m = 0; m < TM; m++)
#pragma unroll
                for (int n = 0; n < TN; n++) acc[m][n] = fmaf(a[m], b[n], acc[m][n]);
        }
        __syncthreads();
    }

#pragma unroll
    for (int m = 0; m < TM; m++) {
        int gr = block_row + trow * TM + m;
        if (gr < M) {
            float4 v = make_float4(acc[m][0], acc[m][1], acc[m][2], acc[m][3]);
            *reinterpret_cast<float4*>(&C[(long long)gr * N + block_col + tcol * TN]) = v;
        }
    }
}

// Hidden/intermediate activations
__device__ __align__(16) float g_h1[(size_t)MAX_N * HID];
__device__ __align__(16) float g_agg1[(size_t)MAX_N * HID];
__device__ __align__(16) float g_h2[(size_t)MAX_N * OUTD];

// ---------------------------------------------------------------------------
// Launch
// ---------------------------------------------------------------------------
extern "C" void kernel_launch(void* const* d_in, const int* in_sizes, int n_in,
                              void* d_out, int out_size) {
    const float* x = (const float*)d_in[0];
    const void* ei = d_in[1];              // int32 or int64 — detected on device
    const float* W1 = (const float*)d_in[2];
    const float* b1 = (const float*)d_in[3];
    const float* W2 = (const float*)d_in[4];
    const float* b2 = (const float*)d_in[5];
    float* out = (float*)d_out;

    const int Nn = in_sizes[0] / IN_DIM;   // 100000
    const int E = in_sizes[1] / 2;         // 1600000
    const int TB = 256;

    float *h1_p, *agg1_p, *h2_p;
    cudaGetSymbolAddress((void**)&h1_p, g_h1);
    cudaGetSymbolAddress((void**)&agg1_p, g_agg1);
    cudaGetSymbolAddress((void**)&h2_p, g_h2);

    // Stage + convert edge indices once
    detect_idx_kernel<<<1, 256>>>(ei, E);
    copy_idx_kernel<<<(E + TB - 1) / TB, TB>>>(ei, E);

    // CSR build by dst (int atomics only)
    zero_deg_kernel<<<(Nn + TB - 1) / TB, TB>>>(Nn);
    count_kernel<<<(E + TB - 1) / TB, TB>>>(E, Nn);
    node_setup_kernel<<<(Nn + TB - 1) / TB, TB>>>(Nn);
    fill_kernel<<<(E + TB - 1) / TB, TB>>>(E, Nn);

    // Layer 1: h1 = x @ W1 (reads x, W1 straight from harness buffers)
    {
        dim3 grid(HID / 64, (Nn + 63) / 64);
        sgemm_kernel<64, 64, 32, 8, 4><<<grid, 128>>>(Nn, HID, IN_DIM, x, W1, h1_p);
    }
    // agg1 = relu(self + gather + b1)   [atomic-free]
    {
        int warps_per_block = TB / 32;
        int blocks = (Nn + warps_per_block - 1) / warps_per_block;
        gather1_kernel<<<blocks, TB>>>(h1_p, b1, agg1_p, Nn);
    }

    // Layer 2: h2 = agg1 @ W2
    {
        dim3 grid(OUTD / 64, (Nn + 63) / 64);
        sgemm_kernel<64, 64, 32, 8, 4><<<grid, 128>>>(Nn, OUTD, HID, agg1_p, W2, h2_p);
    }
    // out = self + gather + b2  (plain stores into d_out)
    {
        int warps_per_block = TB / 32;
        int blocks = (Nn + warps_per_block - 1) / warps_per_block;
        gather2_kernel<<<blocks, TB>>>(h2_p, b2, out, Nn);
    }
}

// round 8
// speedup vs baseline: 3.0271x; 1.1405x over previous
#include <cuda_runtime.h>
#include <cuda_bf16.h>
#include <mma.h>

using namespace nvcuda;

#define MAX_N 100000
#define PAD_N (MAX_N + 64)
#define MAX_E 1600000
#define IN_DIM 256
#define HID 128
#define OUTD 64

// Scratch in device globals. Atomics touch ONLY these.
__device__ __align__(16) int   g_src[MAX_E];
__device__ __align__(16) int   g_dst[MAX_E];
__device__ __align__(16) int   g_deg[MAX_N];
__device__ __align__(16) int   g_rowstart[MAX_N];
__device__ __align__(16) int   g_cursor[MAX_N];
__device__ __align__(16) int2  g_csr[MAX_E];       // (src, __float_as_int(w))
__device__ __align__(16) float g_dinv[MAX_N];
__device__ int g_total;
__device__ int g_is_i32;

// Activations (row-padded so wmma stores need no guards; padded rows unread)
__device__ __align__(16) float g_h1[(size_t)PAD_N * HID];
__device__ __align__(16) float g_agg1[(size_t)PAD_N * HID];
__device__ __align__(16) float g_h2[(size_t)PAD_N * OUTD];

// ---------------------------------------------------------------------------
// Edge-index dtype detection + fused stage/count
// ---------------------------------------------------------------------------
__global__ void detect_idx_kernel(const void* __restrict__ ei, int E) {
    const unsigned long long* p = (const unsigned long long*)ei;
    __shared__ int found;
    if (threadIdx.x == 0) found = 0;
    __syncthreads();
    int lim = E < 4096 ? E : 4096;
    for (int j = threadIdx.x; j < lim; j += blockDim.x) {
        if ((p[j] >> 32) != 0ULL) found = 1;
    }
    __syncthreads();
    if (threadIdx.x == 0) g_is_i32 = found;
}

__global__ void zero_deg_kernel(int n) {
    int i = blockIdx.x * blockDim.x + threadIdx.x;
    if (i < n) g_deg[i] = 0;
    if (i == 0) g_total = 0;
}

// decode edge indices + count degree, single pass
__global__ void stage_count_kernel(const void* __restrict__ ei, int E, int n) {
    int e = blockIdx.x * blockDim.x + threadIdx.x;
    if (e >= E) return;
    int s, d;
    if (g_is_i32) {
        const int* p = (const int*)ei;
        s = p[e];
        d = p[E + e];
    } else {
        const long long* p = (const long long*)ei;
        s = (int)p[e];
        d = (int)p[E + e];
    }
    g_src[e] = s;
    g_dst[e] = d;
    if ((unsigned)d < (unsigned)n) atomicAdd(&g_deg[d], 1);
}

__global__ void node_setup_kernel(int n) {
    int i = blockIdx.x * blockDim.x + threadIdx.x;
    if (i < n) {
        int d = g_deg[i];
        g_dinv[i] = rsqrtf((float)d + 1.0f);
        int base = atomicAdd(&g_total, d);
        g_rowstart[i] = base;
        g_cursor[i] = base;
    }
}

__global__ void fill_kernel(int E, int n) {
    int e = blockIdx.x * blockDim.x + threadIdx.x;
    if (e >= E) return;
    unsigned s = (unsigned)g_src[e];
    unsigned d = (unsigned)g_dst[e];
    if (s >= (unsigned)n || d >= (unsigned)n) return;
    float w = g_dinv[s] * g_dinv[d];
    int pos = atomicAdd(&g_cursor[d], 1);
    g_csr[pos] = make_int2((int)s, __float_as_int(w));
}

// ---------------------------------------------------------------------------
// Warp-per-node gather aggregation (atomic-free)
// ---------------------------------------------------------------------------
__global__ void gather1_kernel(const float* __restrict__ h,
                               const float* __restrict__ b1,
                               float* __restrict__ aggout, int n) {
    int warp = (int)((blockIdx.x * blockDim.x + threadIdx.x) >> 5);
    int lane = threadIdx.x & 31;
    if (warp >= n) return;
    const float4* hp = (const float4*)h;
    int start = g_rowstart[warp];
    int len = g_deg[warp];
    float di = g_dinv[warp];
    float s2 = di * di;
    float4 acc = hp[(long long)warp * 32 + lane];
    acc.x *= s2; acc.y *= s2; acc.z *= s2; acc.w *= s2;
    const int2* __restrict__ csr = g_csr + start;
    #pragma unroll 2
    for (int j = 0; j < len; j++) {
        int2 ed = csr[j];
        float w = __int_as_float(ed.y);
        float4 v = hp[(long long)ed.x * 32 + lane];
        acc.x = fmaf(v.x, w, acc.x);
        acc.y = fmaf(v.y, w, acc.y);
        acc.z = fmaf(v.z, w, acc.z);
        acc.w = fmaf(v.w, w, acc.w);
    }
    float4 bb = ((const float4*)b1)[lane];
    acc.x = fmaxf(acc.x + bb.x, 0.0f);
    acc.y = fmaxf(acc.y + bb.y, 0.0f);
    acc.z = fmaxf(acc.z + bb.z, 0.0f);
    acc.w = fmaxf(acc.w + bb.w, 0.0f);
    ((float4*)aggout)[(long long)warp * 32 + lane] = acc;
}

__global__ void gather2_kernel(const float* __restrict__ h,
                               const float* __restrict__ b2,
                               float* __restrict__ out, int n) {
    int warp = (int)((blockIdx.x * blockDim.x + threadIdx.x) >> 5);
    int lane = threadIdx.x & 31;
    if (warp >= n) return;
    const float2* hp = (const float2*)h;
    int start = g_rowstart[warp];
    int len = g_deg[warp];
    float di = g_dinv[warp];
    float s2 = di * di;
    float2 acc = hp[(long long)warp * 32 + lane];
    acc.x *= s2; acc.y *= s2;
    const int2* __restrict__ csr = g_csr + start;
    #pragma unroll 2
    for (int j = 0; j < len; j++) {
        int2 ed = csr[j];
        float w = __int_as_float(ed.y);
        float2 v = hp[(long long)ed.x * 32 + lane];
        acc.x = fmaf(v.x, w, acc.x);
        acc.y = fmaf(v.y, w, acc.y);
    }
    float2 bb = ((const float2*)b2)[lane];
    acc.x += bb.x;
    acc.y += bb.y;
    ((float2*)out)[(long long)warp * 32 + lane] = acc;
}

// ---------------------------------------------------------------------------
// TF32 tensor-core GEMM: C[M,N] = A[M,K] @ B[K,N]
// 64x64 block tile, BK=32, 128 threads = 4 warps (2x2), each warp 32x32
// via 2x2 wmma 16x16x8 fragments. A-row loads guarded; C rows padded.
// ---------------------------------------------------------------------------
__global__ void tf32_gemm_kernel(int M, int N, int K,
                                 const float* __restrict__ A,
                                 const float* __restrict__ B,
                                 float* __restrict__ C) {
    constexpr int BM = 64, BN = 64, BK = 32;
    constexpr int LDA = BK + 8;   // 40, mult of 8
    constexpr int LDB = BN + 8;   // 72, mult of 8
    __shared__ float As[BM * LDA];
    __shared__ float Bs[BK * LDB];

    const int tid = threadIdx.x;
    const int wid = tid >> 5;
    const int wm = wid >> 1;       // warp row 0..1
    const int wn = wid & 1;        // warp col 0..1
    const int row0 = blockIdx.y * BM;
    const int col0 = blockIdx.x * BN;

    wmma::fragment<wmma::accumulator, 16, 16, 8, float> acc[2][2];
#pragma unroll
    for (int i = 0; i < 2; i++)
#pragma unroll
        for (int j = 0; j < 2; j++) wmma::fill_fragment(acc[i][j], 0.0f);

    for (int k0 = 0; k0 < K; k0 += BK) {
        // A tile 64x32: 512 float4, 4 per thread
#pragma unroll
        for (int i = 0; i < 4; i++) {
            int lin = tid + i * 128;       // float4 idx
            int r = lin >> 3;              // /8 (32 floats = 8 f4 per row)
            int c4 = (lin & 7) << 2;
            float4 v = make_float4(0.f, 0.f, 0.f, 0.f);
            if (row0 + r < M)
                v = *reinterpret_cast<const float4*>(&A[(long long)(row0 + r) * K + k0 + c4]);
            As[r * LDA + c4 + 0] = v.x;
            As[r * LDA + c4 + 1] = v.y;
            As[r * LDA + c4 + 2] = v.z;
            As[r * LDA + c4 + 3] = v.w;
        }
        // B tile 32x64: 512 float4
#pragma unroll
        for (int i = 0; i < 4; i++) {
            int lin = tid + i * 128;
            int kk = lin >> 4;             // /16 (64 floats = 16 f4 per row)
            int c4 = (lin & 15) << 2;
            float4 v = *reinterpret_cast<const float4*>(&B[(long long)(k0 + kk) * N + col0 + c4]);
            Bs[kk * LDB + c4 + 0] = v.x;
            Bs[kk * LDB + c4 + 1] = v.y;
            Bs[kk * LDB + c4 + 2] = v.z;
            Bs[kk * LDB + c4 + 3] = v.w;
        }
        __syncthreads();

#pragma unroll
        for (int ks = 0; ks < BK; ks += 8) {
            wmma::fragment<wmma::matrix_a, 16, 16, 8, wmma::precision::tf32, wmma::row_major> af[2];
            wmma::fragment<wmma::matrix_b, 16, 16, 8, wmma::precision::tf32, wmma::row_major> bf[2];
#pragma unroll
            for (int i = 0; i < 2; i++) {
                wmma::load_matrix_sync(af[i], &As[(wm * 32 + i * 16) * LDA + ks], LDA);
#pragma unroll
                for (int t = 0; t < af[i].num_elements; t++)
                    af[i].x[t] = wmma::__float_to_tf32(af[i].x[t]);
            }
#pragma unroll
            for (int j = 0; j < 2; j++) {
                wmma::load_matrix_sync(bf[j], &Bs[ks * LDB + wn * 32 + j * 16], LDB);
#pragma unroll
                for (int t = 0; t < bf[j].num_elements; t++)
                    bf[j].x[t] = wmma::__float_to_tf32(bf[j].x[t]);
            }
#pragma unroll
            for (int i = 0; i < 2; i++)
#pragma unroll
                for (int j = 0; j < 2; j++)
                    wmma::mma_sync(acc[i][j], af[i], bf[j], acc[i][j]);
        }
        __syncthreads();
    }

    // C is row-padded device scratch: unguarded full-tile stores are safe.
#pragma unroll
    for (int i = 0; i < 2; i++)
#pragma unroll
        for (int j = 0; j < 2; j++) {
            int r = row0 + wm * 32 + i * 16;
            int c = col0 + wn * 32 + j * 16;
            wmma::store_matrix_sync(&C[(long long)r * N + c], acc[i][j], N, wmma::mem_row_major);
        }
}

// ---------------------------------------------------------------------------
// Launch
// ---------------------------------------------------------------------------
extern "C" void kernel_launch(void* const* d_in, const int* in_sizes, int n_in,
                              void* d_out, int out_size) {
    const float* x = (const float*)d_in[0];
    const void* ei = d_in[1];
    const float* W1 = (const float*)d_in[2];
    const float* b1 = (const float*)d_in[3];
    const float* W2 = (const float*)d_in[4];
    const float* b2 = (const float*)d_in[5];
    float* out = (float*)d_out;

    const int Nn = in_sizes[0] / IN_DIM;   // 100000
    const int E = in_sizes[1] / 2;         // 1600000
    const int TB = 256;

    float *h1_p, *agg1_p, *h2_p;
    cudaGetSymbolAddress((void**)&h1_p, g_h1);
    cudaGetSymbolAddress((void**)&agg1_p, g_agg1);
    cudaGetSymbolAddress((void**)&h2_p, g_h2);

    // Stage + CSR build
    detect_idx_kernel<<<1, 256>>>(ei, E);
    zero_deg_kernel<<<(Nn + TB - 1) / TB, TB>>>(Nn);
    stage_count_kernel<<<(E + TB - 1) / TB, TB>>>(ei, E, Nn);
    node_setup_kernel<<<(Nn + TB - 1) / TB, TB>>>(Nn);
    fill_kernel<<<(E + TB - 1) / TB, TB>>>(E, Nn);

    // Layer 1: h1 = x @ W1 (tf32 tensor cores)
    {
        dim3 grid(HID / 64, (Nn + 63) / 64);
        tf32_gemm_kernel<<<grid, 128>>>(Nn, HID, IN_DIM, x, W1, h1_p);
    }
    {
        int warps_per_block = TB / 32;
        int blocks = (Nn + warps_per_block - 1) / warps_per_block;
        gather1_kernel<<<blocks, TB>>>(h1_p, b1, agg1_p, Nn);
    }

    // Layer 2: h2 = agg1 @ W2 (tf32 tensor cores)
    {
        dim3 grid(OUTD / 64, (Nn + 63) / 64);
        tf32_gemm_kernel<<<grid, 128>>>(Nn, OUTD, HID, agg1_p, W2, h2_p);
    }
    {
        int warps_per_block = TB / 32;
        int blocks = (Nn + warps_per_block - 1) / warps_per_block;
        gather2_kernel<<<blocks, TB>>>(h2_p, b2, out, Nn);
    }
}

// round 9
// speedup vs baseline: 3.2733x; 1.0814x over previous
#include <cuda_runtime.h>
#include <cuda_fp16.h>
#include <mma.h>

using namespace nvcuda;

#define MAX_N 100000
#define PAD_N (MAX_N + 64)
#define MAX_E 1600000
#define IN_DIM 256
#define HID 128
#define OUTD 64

// Scratch in device globals. Atomics touch ONLY these.
__device__ __align__(16) int    g_deg[MAX_N];
__device__ __align__(16) int    g_rowstart[MAX_N];
__device__ __align__(16) int    g_cursor[MAX_N];
__device__ __align__(16) int2   g_csr[MAX_E];      // (src, __float_as_int(w))
__device__ __align__(16) float  g_dinv[MAX_N];
__device__ int g_total;
__device__ int g_is_i32;

// Activations in fp16 (halves gather L2 traffic); rows padded for unguarded stores
__device__ __align__(16) __half g_h1[(size_t)PAD_N * HID];
__device__ __align__(16) __half g_agg1[(size_t)PAD_N * HID];
__device__ __align__(16) __half g_h2[(size_t)PAD_N * OUTD];
__device__ __align__(16) __half g_W2h[HID * OUTD];

// ---------------------------------------------------------------------------
// Edge-index dtype detection (JAX may emit int32 despite int64 in source)
// ---------------------------------------------------------------------------
__global__ void detect_idx_kernel(const void* __restrict__ ei, int E) {
    const unsigned long long* p = (const unsigned long long*)ei;
    __shared__ int found;
    if (threadIdx.x == 0) found = 0;
    __syncthreads();
    int lim = E < 4096 ? E : 4096;
    for (int j = threadIdx.x; j < lim; j += blockDim.x)
        if ((p[j] >> 32) != 0ULL) found = 1;
    __syncthreads();
    if (threadIdx.x == 0) g_is_i32 = found;
}

__global__ void zero_deg_kernel(int n) {
    int i = blockIdx.x * blockDim.x + threadIdx.x;
    if (i < n) g_deg[i] = 0;
    if (i == 0) g_total = 0;
}

// degree count straight from the harness edge buffer (plain loads)
__global__ void count_kernel(const void* __restrict__ ei, int E, int n) {
    int e = blockIdx.x * blockDim.x + threadIdx.x;
    if (e >= E) return;
    int d = g_is_i32 ? ((const int*)ei)[E + e] : (int)((const long long*)ei)[E + e];
    if ((unsigned)d < (unsigned)n) atomicAdd(&g_deg[d], 1);
}

__global__ void node_setup_kernel(int n) {
    int i = blockIdx.x * blockDim.x + threadIdx.x;
    if (i < n) {
        int d = g_deg[i];
        g_dinv[i] = rsqrtf((float)d + 1.0f);
        int base = atomicAdd(&g_total, d);
        g_rowstart[i] = base;
        g_cursor[i] = base;
    }
}

__global__ void fill_kernel(const void* __restrict__ ei, int E, int n) {
    int e = blockIdx.x * blockDim.x + threadIdx.x;
    if (e >= E) return;
    int s, d;
    if (g_is_i32) {
        const int* p = (const int*)ei;
        s = p[e]; d = p[E + e];
    } else {
        const long long* p = (const long long*)ei;
        s = (int)p[e]; d = (int)p[E + e];
    }
    if ((unsigned)s >= (unsigned)n || (unsigned)d >= (unsigned)n) return;
    float w = g_dinv[s] * g_dinv[d];
    int pos = atomicAdd(&g_cursor[d], 1);
    g_csr[pos] = make_int2(s, __float_as_int(w));
}

__global__ void w2_convert_kernel(const float* __restrict__ W2) {
    int i = blockIdx.x * blockDim.x + threadIdx.x;
    if (i < HID * OUTD) g_W2h[i] = __float2half(W2[i]);
}

// ---------------------------------------------------------------------------
// Warp-per-node gathers (atomic-free, fp16 in / fp32 accumulate)
// ---------------------------------------------------------------------------
// dim=128: lane owns cols [4*lane,4*lane+4) = 2 half2. 256B per row-read/warp.
__global__ void gather1_kernel(const float* __restrict__ b1, int n) {
    int warp = (int)((blockIdx.x * blockDim.x + threadIdx.x) >> 5);
    int lane = threadIdx.x & 31;
    if (warp >= n) return;
    const __half2* hp = (const __half2*)g_h1;
    int start = g_rowstart[warp];
    int len = g_deg[warp];
    float di = g_dinv[warp];
    float s2 = di * di;
    long long self = (long long)warp * 64 + 2 * lane;
    float2 a0 = __half22float2(hp[self]);
    float2 a1 = __half22float2(hp[self + 1]);
    float4 acc = make_float4(a0.x * s2, a0.y * s2, a1.x * s2, a1.y * s2);
    const int2* __restrict__ csr = g_csr + start;
    #pragma unroll 2
    for (int j = 0; j < len; j++) {
        int2 ed = csr[j];
        float w = __int_as_float(ed.y);
        long long base = (long long)ed.x * 64 + 2 * lane;
        float2 v0 = __half22float2(hp[base]);
        float2 v1 = __half22float2(hp[base + 1]);
        acc.x = fmaf(v0.x, w, acc.x);
        acc.y = fmaf(v0.y, w, acc.y);
        acc.z = fmaf(v1.x, w, acc.z);
        acc.w = fmaf(v1.y, w, acc.w);
    }
    float4 bb = ((const float4*)b1)[lane];
    acc.x = fmaxf(acc.x + bb.x, 0.0f);
    acc.y = fmaxf(acc.y + bb.y, 0.0f);
    acc.z = fmaxf(acc.z + bb.z, 0.0f);
    acc.w = fmaxf(acc.w + bb.w, 0.0f);
    __half2* op = (__half2*)g_agg1;
    op[self] = __floats2half2_rn(acc.x, acc.y);
    op[self + 1] = __floats2half2_rn(acc.z, acc.w);
}

// dim=64: lane owns cols [2*lane,2*lane+2) = 1 half2. fp32 out to d_out.
__global__ void gather2_kernel(const float* __restrict__ b2,
                               float* __restrict__ out, int n) {
    int warp = (int)((blockIdx.x * blockDim.x + threadIdx.x) >> 5);
    int lane = threadIdx.x & 31;
    if (warp >= n) return;
    const __half2* hp = (const __half2*)g_h2;
    int start = g_rowstart[warp];
    int len = g_deg[warp];
    float di = g_dinv[warp];
    float s2 = di * di;
    long long self = (long long)warp * 32 + lane;
    float2 acc = __half22float2(hp[self]);
    acc.x *= s2; acc.y *= s2;
    const int2* __restrict__ csr = g_csr + start;
    #pragma unroll 2
    for (int j = 0; j < len; j++) {
        int2 ed = csr[j];
        float w = __int_as_float(ed.y);
        float2 v = __half22float2(hp[(long long)ed.x * 32 + lane]);
        acc.x = fmaf(v.x, w, acc.x);
        acc.y = fmaf(v.y, w, acc.y);
    }
    float2 bb = ((const float2*)b2)[lane];
    acc.x += bb.x;
    acc.y += bb.y;
    ((float2*)out)[self] = acc;
}

// ---------------------------------------------------------------------------
// GEMM1: tf32 tensor cores, fp32 A/B in, fp16 C out (smem-staged epilogue).
// 64x64 tile, BK=32, 128 threads (4 warps 2x2).
// ---------------------------------------------------------------------------
__global__ void tf32_gemm_h_kernel(int M, int N, int K,
                                   const float* __restrict__ A,
                                   const float* __restrict__ B,
                                   __half* __restrict__ C) {
    constexpr int BM = 64, BN = 64, BK = 32;
    constexpr int LDA = BK + 8, LDB = BN + 8;
    __shared__ float As[BM * LDA];
    __shared__ float Bs[BK * LDB];
    __shared__ float Cs[BM * BN];

    const int tid = threadIdx.x;
    const int wid = tid >> 5;
    const int wm = wid >> 1, wn = wid & 1;
    const int row0 = blockIdx.y * BM;
    const int col0 = blockIdx.x * BN;

    wmma::fragment<wmma::accumulator, 16, 16, 8, float> acc[2][2];
#pragma unroll
    for (int i = 0; i < 2; i++)
#pragma unroll
        for (int j = 0; j < 2; j++) wmma::fill_fragment(acc[i][j], 0.0f);

    for (int k0 = 0; k0 < K; k0 += BK) {
#pragma unroll
        for (int i = 0; i < 4; i++) {
            int lin = tid + i * 128;
            int r = lin >> 3;
            int c4 = (lin & 7) << 2;
            float4 v = make_float4(0.f, 0.f, 0.f, 0.f);
            if (row0 + r < M)
                v = *reinterpret_cast<const float4*>(&A[(long long)(row0 + r) * K + k0 + c4]);
            As[r * LDA + c4 + 0] = v.x;
            As[r * LDA + c4 + 1] = v.y;
            As[r * LDA + c4 + 2] = v.z;
            As[r * LDA + c4 + 3] = v.w;
        }
#pragma unroll
        for (int i = 0; i < 4; i++) {
            int lin = tid + i * 128;
            int kk = lin >> 4;
            int c4 = (lin & 15) << 2;
            float4 v = *reinterpret_cast<const float4*>(&B[(long long)(k0 + kk) * N + col0 + c4]);
            Bs[kk * LDB + c4 + 0] = v.x;
            Bs[kk * LDB + c4 + 1] = v.y;
            Bs[kk * LDB + c4 + 2] = v.z;
            Bs[kk * LDB + c4 + 3] = v.w;
        }
        __syncthreads();

#pragma unroll
        for (int ks = 0; ks < BK; ks += 8) {
            wmma::fragment<wmma::matrix_a, 16, 16, 8, wmma::precision::tf32, wmma::row_major> af[2];
            wmma::fragment<wmma::matrix_b, 16, 16, 8, wmma::precision::tf32, wmma::row_major> bf[2];
#pragma unroll
            for (int i = 0; i < 2; i++) {
                wmma::load_matrix_sync(af[i], &As[(wm * 32 + i * 16) * LDA + ks], LDA);
#pragma unroll
                for (int t = 0; t < af[i].num_elements; t++)
                    af[i].x[t] = wmma::__float_to_tf32(af[i].x[t]);
            }
#pragma unroll
            for (int j = 0; j < 2; j++) {
                wmma::load_matrix_sync(bf[j], &Bs[ks * LDB + wn * 32 + j * 16], LDB);
#pragma unroll
                for (int t = 0; t < bf[j].num_elements; t++)
                    bf[j].x[t] = wmma::__float_to_tf32(bf[j].x[t]);
            }
#pragma unroll
            for (int i = 0; i < 2; i++)
#pragma unroll
                for (int j = 0; j < 2; j++)
                    wmma::mma_sync(acc[i][j], af[i], bf[j], acc[i][j]);
        }
        __syncthreads();
    }

    // Stage to smem, convert to fp16, store (C row-padded: no guards needed)
#pragma unroll
    for (int i = 0; i < 2; i++)
#pragma unroll
        for (int j = 0; j < 2; j++)
            wmma::store_matrix_sync(&Cs[(wm * 32 + i * 16) * BN + wn * 32 + j * 16],
                                    acc[i][j], BN, wmma::mem_row_major);
    __syncthreads();
    __half2* C2 = (__half2*)C;
    int ldc2 = N >> 1;
#pragma unroll
    for (int i = 0; i < 16; i++) {
        int lin = tid + i * 128;            // half2 index within 64x64 tile
        int r = lin >> 5;                   // 32 half2 per row
        int c2 = lin & 31;
        float lo = Cs[r * BN + 2 * c2];
        float hi = Cs[r * BN + 2 * c2 + 1];
        C2[(long long)(row0 + r) * ldc2 + (col0 >> 1) + c2] = __floats2half2_rn(lo, hi);
    }
}

// ---------------------------------------------------------------------------
// GEMM2: fp16 wmma m16n16k16, A=g_agg1 [M,128] half, B=g_W2h [128,64] half,
// C=g_h2 [M,64] half. 64x64 tile, BK=32, 128 threads.
// ---------------------------------------------------------------------------
__global__ void h16_gemm_kernel(int M) {
    constexpr int K = HID, N = OUTD;
    constexpr int BM = 64, BN = 64, BK = 32;
    constexpr int LDA = BK + 8, LDB = BN + 8;
    __shared__ __half Ah[BM * LDA];
    __shared__ __half Bh[BK * LDB];
    __shared__ float Cs[BM * BN];

    const int tid = threadIdx.x;
    const int wid = tid >> 5;
    const int wm = wid >> 1, wn = wid & 1;
    const int row0 = blockIdx.x * BM;

    wmma::fragment<wmma::accumulator, 16, 16, 16, float> acc[2][2];
#pragma unroll
    for (int i = 0; i < 2; i++)
#pragma unroll
        for (int j = 0; j < 2; j++) wmma::fill_fragment(acc[i][j], 0.0f);

    const __half* A = g_agg1;   // PAD_N rows: unguarded tile loads are safe
    for (int k0 = 0; k0 < K; k0 += BK) {
        // A tile 64x32 half: 256 uint4 (8 half each), 2 per thread
#pragma unroll
        for (int i = 0; i < 2; i++) {
            int lin = tid + i * 128;
            int r = lin >> 2;
            int c8 = (lin & 3) << 3;
            uint4 v = *reinterpret_cast<const uint4*>(&A[(long long)(row0 + r) * K + k0 + c8]);
            *reinterpret_cast<uint4*>(&Ah[r * LDA + c8]) = v;
        }
        // B tile 32x64 half: 256 uint4, 2 per thread
#pragma unroll
        for (int i = 0; i < 2; i++) {
            int lin = tid + i * 128;
            int kk = lin >> 3;
            int c8 = (lin & 7) << 3;
            uint4 v = *reinterpret_cast<const uint4*>(&g_W2h[(k0 + kk) * N + c8]);
            *reinterpret_cast<uint4*>(&Bh[kk * LDB + c8]) = v;
        }
        __syncthreads();

#pragma unroll
        for (int ks = 0; ks < BK; ks += 16) {
            wmma::fragment<wmma::matrix_a, 16, 16, 16, __half, wmma::row_major> af[2];
            wmma::fragment<wmma::matrix_b, 16, 16, 16, __half, wmma::row_major> bf[2];
#pragma unroll
            for (int i = 0; i < 2; i++)
                wmma::load_matrix_sync(af[i], &Ah[(wm * 32 + i * 16) * LDA + ks], LDA);
#pragma unroll
            for (int j = 0; j < 2; j++)
                wmma::load_matrix_sync(bf[j], &Bh[ks * LDB + wn * 32 + j * 16], LDB);
#pragma unroll
            for (int i = 0; i < 2; i++)
#pragma unroll
                for (int j = 0; j < 2; j++)
                    wmma::mma_sync(acc[i][j], af[i], bf[j], acc[i][j]);
        }
        __syncthreads();
    }

#pragma unroll
    for (int i = 0; i < 2; i++)
#pragma unroll
        for (int j = 0; j < 2; j++)
            wmma::store_matrix_sync(&Cs[(wm * 32 + i * 16) * BN + wn * 32 + j * 16],
                                    acc[i][j], BN, wmma::mem_row_major);
    __syncthreads();
    __half2* C2 = (__half2*)g_h2;
#pragma unroll
    for (int i = 0; i < 16; i++) {
        int lin = tid + i * 128;
        int r = lin >> 5;
        int c2 = lin & 31;
        float lo = Cs[r * BN + 2 * c2];
        float hi = Cs[r * BN + 2 * c2 + 1];
        C2[(long long)(row0 + r) * (N >> 1) + c2] = __floats2half2_rn(lo, hi);
    }
}

// ---------------------------------------------------------------------------
// Launch
// ---------------------------------------------------------------------------
extern "C" void kernel_launch(void* const* d_in, const int* in_sizes, int n_in,
                              void* d_out, int out_size) {
    const float* x = (const float*)d_in[0];
    const void* ei = d_in[1];
    const float* W1 = (const float*)d_in[2];
    const float* b1 = (const float*)d_in[3];
    const float* W2 = (const float*)d_in[4];
    const float* b2 = (const float*)d_in[5];
    float* out = (float*)d_out;

    const int Nn = in_sizes[0] / IN_DIM;   // 100000
    const int E = in_sizes[1] / 2;         // 1600000
    const int TB = 256;

    __half* h1_p;
    cudaGetSymbolAddress((void**)&h1_p, g_h1);

    // CSR build (reads harness ei directly; no staging pass)
    detect_idx_kernel<<<1, 256>>>(ei, E);
    zero_deg_kernel<<<(Nn + TB - 1) / TB, TB>>>(Nn);
    count_kernel<<<(E + TB - 1) / TB, TB>>>(ei, E, Nn);
    node_setup_kernel<<<(Nn + TB - 1) / TB, TB>>>(Nn);
    fill_kernel<<<(E + TB - 1) / TB, TB>>>(ei, E, Nn);
    w2_convert_kernel<<<(HID * OUTD + TB - 1) / TB, TB>>>(W2);

    // Layer 1: h1 = x @ W1 (tf32 -> fp16 out)
    {
        dim3 grid(HID / 64, (Nn + 63) / 64);
        tf32_gemm_h_kernel<<<grid, 128>>>(Nn, HID, IN_DIM, x, W1, h1_p);
    }
    {
        int blocks = (Nn + (TB / 32) - 1) / (TB / 32);
        gather1_kernel<<<blocks, TB>>>(b1, Nn);
    }

    // Layer 2: h2 = agg1 @ W2 (fp16 wmma)
    h16_gemm_kernel<<<(Nn + 63) / 64, 128>>>(Nn);
    {
        int blocks = (Nn + (TB / 32) - 1) / (TB / 32);
        gather2_kernel<<<blocks, TB>>>(b2, out, Nn);
    }
}

// round 10
// speedup vs baseline: 3.5068x; 1.0713x over previous
#include <cuda_runtime.h>
#include <cuda_fp16.h>
#include <mma.h>

using namespace nvcuda;

#define MAX_N 100000
#define PAD_N (MAX_N + 64)
#define MAX_E 1600000
#define IN_DIM 256
#define HID 128
#define OUTD 64

// Scratch in device globals. Atomics touch ONLY these.
__device__ __align__(16) int    g_deg[MAX_N];
__device__ __align__(16) int    g_rowstart[MAX_N];
__device__ __align__(16) int    g_cursor[MAX_N];
__device__ __align__(16) int2   g_csr[MAX_E];      // (src, __float_as_int(w))
__device__ __align__(16) float  g_dinv[MAX_N];
__device__ int g_total;
__device__ int g_is_i32;

// Activations in fp16; rows padded for unguarded wmma stores
__device__ __align__(16) __half g_h1[(size_t)PAD_N * HID];
__device__ __align__(16) __half g_agg1[(size_t)PAD_N * HID];
__device__ __align__(16) __half g_h2[(size_t)PAD_N * OUTD];
__device__ __align__(16) __half g_W2h[HID * OUTD];

// ---------------------------------------------------------------------------
// Fused init: zero degrees, detect edge dtype (block 0), convert W2 to fp16.
// ---------------------------------------------------------------------------
__global__ void init_kernel(const void* __restrict__ ei, const float* __restrict__ W2,
                            int E, int n) {
    int i = blockIdx.x * blockDim.x + threadIdx.x;
    if (i < n) g_deg[i] = 0;
    if (i < HID * OUTD) g_W2h[i] = __float2half(W2[i]);
    if (i == 0) g_total = 0;
    if (blockIdx.x == 0) {
        // dtype detect: high words of first 4096 u64 reads are all zero iff int64
        const unsigned long long* p = (const unsigned long long*)ei;
        __shared__ int found;
        if (threadIdx.x == 0) found = 0;
        __syncthreads();
        int lim = E < 4096 ? E : 4096;
        for (int j = threadIdx.x; j < lim; j += blockDim.x)
            if ((p[j] >> 32) != 0ULL) found = 1;
        __syncthreads();
        if (threadIdx.x == 0) g_is_i32 = found;
    }
}

__global__ void count_kernel(const void* __restrict__ ei, int E, int n) {
    int e = blockIdx.x * blockDim.x + threadIdx.x;
    if (e >= E) return;
    int d = g_is_i32 ? ((const int*)ei)[E + e] : (int)((const long long*)ei)[E + e];
    if ((unsigned)d < (unsigned)n) atomicAdd(&g_deg[d], 1);
}

__global__ void node_setup_kernel(int n) {
    int i = blockIdx.x * blockDim.x + threadIdx.x;
    if (i < n) {
        int d = g_deg[i];
        g_dinv[i] = rsqrtf((float)d + 1.0f);
        int base = atomicAdd(&g_total, d);
        g_rowstart[i] = base;
        g_cursor[i] = base;
    }
}

__global__ void fill_kernel(const void* __restrict__ ei, int E, int n) {
    int e = blockIdx.x * blockDim.x + threadIdx.x;
    if (e >= E) return;
    int s, d;
    if (g_is_i32) {
        const int* p = (const int*)ei;
        s = p[e]; d = p[E + e];
    } else {
        const long long* p = (const long long*)ei;
        s = (int)p[e]; d = (int)p[E + e];
    }
    if ((unsigned)s >= (unsigned)n || (unsigned)d >= (unsigned)n) return;
    float w = g_dinv[s] * g_dinv[d];
    int pos = atomicAdd(&g_cursor[d], 1);
    g_csr[pos] = make_int2(s, __float_as_int(w));
}

// ---------------------------------------------------------------------------
// Warp-per-node gathers, software-pipelined 2 edges/iter (fp16 in, fp32 acc)
// ---------------------------------------------------------------------------
__global__ void gather1_kernel(const float* __restrict__ b1, int n) {
    int warp = (int)((blockIdx.x * blockDim.x + threadIdx.x) >> 5);
    int lane = threadIdx.x & 31;
    if (warp >= n) return;
    const __half2* __restrict__ hp = (const __half2*)g_h1;
    int start = g_rowstart[warp];
    int len = g_deg[warp];
    float di = g_dinv[warp];
    float s2 = di * di;
    long long self = (long long)warp * 64 + 2 * lane;
    float2 a0 = __half22float2(hp[self]);
    float2 a1 = __half22float2(hp[self + 1]);
    float4 acc = make_float4(a0.x * s2, a0.y * s2, a1.x * s2, a1.y * s2);
    const int2* __restrict__ csr = g_csr + start;

    int j = 0;
    for (; j + 2 <= len; j += 2) {
        // issue all loads before any FMA (MLP=2 edges x 2 half2)
        int2 e0 = csr[j];
        int2 e1 = csr[j + 1];
        long long b0 = (long long)e0.x * 64 + 2 * lane;
        long long b1o = (long long)e1.x * 64 + 2 * lane;
        __half2 p00 = hp[b0], p01 = hp[b0 + 1];
        __half2 p10 = hp[b1o], p11 = hp[b1o + 1];
        float w0 = __int_as_float(e0.y);
        float w1 = __int_as_float(e1.y);
        float2 v;
        v = __half22float2(p00); acc.x = fmaf(v.x, w0, acc.x); acc.y = fmaf(v.y, w0, acc.y);
        v = __half22float2(p01); acc.z = fmaf(v.x, w0, acc.z); acc.w = fmaf(v.y, w0, acc.w);
        v = __half22float2(p10); acc.x = fmaf(v.x, w1, acc.x); acc.y = fmaf(v.y, w1, acc.y);
        v = __half22float2(p11); acc.z = fmaf(v.x, w1, acc.z); acc.w = fmaf(v.y, w1, acc.w);
    }
    if (j < len) {
        int2 e0 = csr[j];
        float w0 = __int_as_float(e0.y);
        long long b0 = (long long)e0.x * 64 + 2 * lane;
        float2 v0 = __half22float2(hp[b0]);
        float2 v1 = __half22float2(hp[b0 + 1]);
        acc.x = fmaf(v0.x, w0, acc.x);
        acc.y = fmaf(v0.y, w0, acc.y);
        acc.z = fmaf(v1.x, w0, acc.z);
        acc.w = fmaf(v1.y, w0, acc.w);
    }
    float4 bb = ((const float4*)b1)[lane];
    acc.x = fmaxf(acc.x + bb.x, 0.0f);
    acc.y = fmaxf(acc.y + bb.y, 0.0f);
    acc.z = fmaxf(acc.z + bb.z, 0.0f);
    acc.w = fmaxf(acc.w + bb.w, 0.0f);
    __half2* op = (__half2*)g_agg1;
    op[self] = __floats2half2_rn(acc.x, acc.y);
    op[self + 1] = __floats2half2_rn(acc.z, acc.w);
}

__global__ void gather2_kernel(const float* __restrict__ b2,
                               float* __restrict__ out, int n) {
    int warp = (int)((blockIdx.x * blockDim.x + threadIdx.x) >> 5);
    int lane = threadIdx.x & 31;
    if (warp >= n) return;
    const __half2* __restrict__ hp = (const __half2*)g_h2;
    int start = g_rowstart[warp];
    int len = g_deg[warp];
    float di = g_dinv[warp];
    float s2 = di * di;
    long long self = (long long)warp * 32 + lane;
    float2 acc = __half22float2(hp[self]);
    acc.x *= s2; acc.y *= s2;
    const int2* __restrict__ csr = g_csr + start;

    int j = 0;
    for (; j + 4 <= len; j += 4) {
        int2 e0 = csr[j], e1 = csr[j + 1], e2 = csr[j + 2], e3 = csr[j + 3];
        __half2 p0 = hp[(long long)e0.x * 32 + lane];
        __half2 p1 = hp[(long long)e1.x * 32 + lane];
        __half2 p2 = hp[(long long)e2.x * 32 + lane];
        __half2 p3 = hp[(long long)e3.x * 32 + lane];
        float2 v;
        v = __half22float2(p0); acc.x = fmaf(v.x, __int_as_float(e0.y), acc.x); acc.y = fmaf(v.y, __int_as_float(e0.y), acc.y);
        v = __half22float2(p1); acc.x = fmaf(v.x, __int_as_float(e1.y), acc.x); acc.y = fmaf(v.y, __int_as_float(e1.y), acc.y);
        v = __half22float2(p2); acc.x = fmaf(v.x, __int_as_float(e2.y), acc.x); acc.y = fmaf(v.y, __int_as_float(e2.y), acc.y);
        v = __half22float2(p3); acc.x = fmaf(v.x, __int_as_float(e3.y), acc.x); acc.y = fmaf(v.y, __int_as_float(e3.y), acc.y);
    }
    for (; j < len; j++) {
        int2 ed = csr[j];
        float w = __int_as_float(ed.y);
        float2 v = __half22float2(hp[(long long)ed.x * 32 + lane]);
        acc.x = fmaf(v.x, w, acc.x);
        acc.y = fmaf(v.y, w, acc.y);
    }
    float2 bb = ((const float2*)b2)[lane];
    acc.x += bb.x;
    acc.y += bb.y;
    ((float2*)out)[self] = acc;
}

// ---------------------------------------------------------------------------
// GEMM1: tf32 wmma, fp32 in, fp16 out. 64x64 tile, BK=32, 128 threads.
// ---------------------------------------------------------------------------
__global__ void tf32_gemm_h_kernel(int M, int N, int K,
                                   const float* __restrict__ A,
                                   const float* __restrict__ B,
                                   __half* __restrict__ C) {
    constexpr int BM = 64, BN = 64, BK = 32;
    constexpr int LDA = BK + 8, LDB = BN + 8;
    __shared__ float As[BM * LDA];
    __shared__ float Bs[BK * LDB];
    __shared__ float Cs[BM * BN];

    const int tid = threadIdx.x;
    const int wid = tid >> 5;
    const int wm = wid >> 1, wn = wid & 1;
    const int row0 = blockIdx.y * BM;
    const int col0 = blockIdx.x * BN;

    wmma::fragment<wmma::accumulator, 16, 16, 8, float> acc[2][2];
#pragma unroll
    for (int i = 0; i < 2; i++)
#pragma unroll
        for (int j = 0; j < 2; j++) wmma::fill_fragment(acc[i][j], 0.0f);

    for (int k0 = 0; k0 < K; k0 += BK) {
#pragma unroll
        for (int i = 0; i < 4; i++) {
            int lin = tid + i * 128;
            int r = lin >> 3;
            int c4 = (lin & 7) << 2;
            float4 v = make_float4(0.f, 0.f, 0.f, 0.f);
            if (row0 + r < M)
                v = *reinterpret_cast<const float4*>(&A[(long long)(row0 + r) * K + k0 + c4]);
            As[r * LDA + c4 + 0] = v.x;
            As[r * LDA + c4 + 1] = v.y;
            As[r * LDA + c4 + 2] = v.z;
            As[r * LDA + c4 + 3] = v.w;
        }
#pragma unroll
        for (int i = 0; i < 4; i++) {
            int lin = tid + i * 128;
            int kk = lin >> 4;
            int c4 = (lin & 15) << 2;
            float4 v = *reinterpret_cast<const float4*>(&B[(long long)(k0 + kk) * N + col0 + c4]);
            Bs[kk * LDB + c4 + 0] = v.x;
            Bs[kk * LDB + c4 + 1] = v.y;
            Bs[kk * LDB + c4 + 2] = v.z;
            Bs[kk * LDB + c4 + 3] = v.w;
        }
        __syncthreads();

#pragma unroll
        for (int ks = 0; ks < BK; ks += 8) {
            wmma::fragment<wmma::matrix_a, 16, 16, 8, wmma::precision::tf32, wmma::row_major> af[2];
            wmma::fragment<wmma::matrix_b, 16, 16, 8, wmma::precision::tf32, wmma::row_major> bf[2];
#pragma unroll
            for (int i = 0; i < 2; i++) {
                wmma::load_matrix_sync(af[i], &As[(wm * 32 + i * 16) * LDA + ks], LDA);
#pragma unroll
                for (int t = 0; t < af[i].num_elements; t++)
                    af[i].x[t] = wmma::__float_to_tf32(af[i].x[t]);
            }
#pragma unroll
            for (int j = 0; j < 2; j++) {
                wmma::load_matrix_sync(bf[j], &Bs[ks * LDB + wn * 32 + j * 16], LDB);
#pragma unroll
                for (int t = 0; t < bf[j].num_elements; t++)
                    bf[j].x[t] = wmma::__float_to_tf32(bf[j].x[t]);
            }
#pragma unroll
            for (int i = 0; i < 2; i++)
#pragma unroll
                for (int j = 0; j < 2; j++)
                    wmma::mma_sync(acc[i][j], af[i], bf[j], acc[i][j]);
        }
        __syncthreads();
    }

#pragma unroll
    for (int i = 0; i < 2; i++)
#pragma unroll
        for (int j = 0; j < 2; j++)
            wmma::store_matrix_sync(&Cs[(wm * 32 + i * 16) * BN + wn * 32 + j * 16],
                                    acc[i][j], BN, wmma::mem_row_major);
    __syncthreads();
    __half2* C2 = (__half2*)C;
    int ldc2 = N >> 1;
#pragma unroll
    for (int i = 0; i < 16; i++) {
        int lin = tid + i * 128;
        int r = lin >> 5;
        int c2 = lin & 31;
        float lo = Cs[r * BN + 2 * c2];
        float hi = Cs[r * BN + 2 * c2 + 1];
        C2[(long long)(row0 + r) * ldc2 + (col0 >> 1) + c2] = __floats2half2_rn(lo, hi);
    }
}

// ---------------------------------------------------------------------------
// GEMM2: fp16 wmma m16n16k16, A=g_agg1, B=g_W2h, C=g_h2. 64x64 tile.
// ---------------------------------------------------------------------------
__global__ void h16_gemm_kernel(int M) {
    constexpr int K = HID, N = OUTD;
    constexpr int BM = 64, BN = 64, BK = 32;
    constexpr int LDA = BK + 8, LDB = BN + 8;
    __shared__ __half Ah[BM * LDA];
    __shared__ __half Bh[BK * LDB];
    __shared__ float Cs[BM * BN];

    const int tid = threadIdx.x;
    const int wid = tid >> 5;
    const int wm = wid >> 1, wn = wid & 1;
    const int row0 = blockIdx.x * BM;

    wmma::fragment<wmma::accumulator, 16, 16, 16, float> acc[2][2];
#pragma unroll
    for (int i = 0; i < 2; i++)
#pragma unroll
        for (int j = 0; j < 2; j++) wmma::fill_fragment(acc[i][j], 0.0f);

    const __half* A = g_agg1;
    for (int k0 = 0; k0 < K; k0 += BK) {
#pragma unroll
        for (int i = 0; i < 2; i++) {
            int lin = tid + i * 128;
            int r = lin >> 2;
            int c8 = (lin & 3) << 3;
            uint4 v = *reinterpret_cast<const uint4*>(&A[(long long)(row0 + r) * K + k0 + c8]);
            *reinterpret_cast<uint4*>(&Ah[r * LDA + c8]) = v;
        }
#pragma unroll
        for (int i = 0; i < 2; i++) {
            int lin = tid + i * 128;
            int kk = lin >> 3;
            int c8 = (lin & 7) << 3;
            uint4 v = *reinterpret_cast<const uint4*>(&g_W2h[(k0 + kk) * N + c8]);
            *reinterpret_cast<uint4*>(&Bh[kk * LDB + c8]) = v;
        }
        __syncthreads();

#pragma unroll
        for (int ks = 0; ks < BK; ks += 16) {
            wmma::fragment<wmma::matrix_a, 16, 16, 16, __half, wmma::row_major> af[2];
            wmma::fragment<wmma::matrix_b, 16, 16, 16, __half, wmma::row_major> bf[2];
#pragma unroll
            for (int i = 0; i < 2; i++)
                wmma::load_matrix_sync(af[i], &Ah[(wm * 32 + i * 16) * LDA + ks], LDA);
#pragma unroll
            for (int j = 0; j < 2; j++)
                wmma::load_matrix_sync(bf[j], &Bh[ks * LDB + wn * 32 + j * 16], LDB);
#pragma unroll
            for (int i = 0; i < 2; i++)
#pragma unroll
                for (int j = 0; j < 2; j++)
                    wmma::mma_sync(acc[i][j], af[i], bf[j], acc[i][j]);
        }
        __syncthreads();
    }

#pragma unroll
    for (int i = 0; i < 2; i++)
#pragma unroll
        for (int j = 0; j < 2; j++)
            wmma::store_matrix_sync(&Cs[(wm * 32 + i * 16) * BN + wn * 32 + j * 16],
                                    acc[i][j], BN, wmma::mem_row_major);
    __syncthreads();
    __half2* C2 = (__half2*)g_h2;
#pragma unroll
    for (int i = 0; i < 16; i++) {
        int lin = tid + i * 128;
        int r = lin >> 5;
        int c2 = lin & 31;
        float lo = Cs[r * BN + 2 * c2];
        float hi = Cs[r * BN + 2 * c2 + 1];
        C2[(long long)(row0 + r) * (N >> 1) + c2] = __floats2half2_rn(lo, hi);
    }
}

// ---------------------------------------------------------------------------
// Launch (ordered so ncu -s 5 -c 1 profiles gather1_kernel, launch #6)
// ---------------------------------------------------------------------------
extern "C" void kernel_launch(void* const* d_in, const int* in_sizes, int n_in,
                              void* d_out, int out_size) {
    const float* x = (const float*)d_in[0];
    const void* ei = d_in[1];
    const float* W1 = (const float*)d_in[2];
    const float* b1 = (const float*)d_in[3];
    const float* W2 = (const float*)d_in[4];
    const float* b2 = (const float*)d_in[5];
    float* out = (float*)d_out;

    const int Nn = in_sizes[0] / IN_DIM;   // 100000
    const int E = in_sizes[1] / 2;         // 1600000
    const int TB = 256;

    __half* h1_p;
    cudaGetSymbolAddress((void**)&h1_p, g_h1);

    // 1: fused init (zero deg + dtype detect + W2 convert)
    init_kernel<<<(Nn + TB - 1) / TB, TB>>>(ei, W2, E, Nn);
    // 2: GEMM1 (independent of CSR)
    {
        dim3 grid(HID / 64, (Nn + 63) / 64);
        tf32_gemm_h_kernel<<<grid, 128>>>(Nn, HID, IN_DIM, x, W1, h1_p);
    }
    // 3-5: CSR build
    count_kernel<<<(E + TB - 1) / TB, TB>>>(ei, E, Nn);
    node_setup_kernel<<<(Nn + TB - 1) / TB, TB>>>(Nn);
    fill_kernel<<<(E + TB - 1) / TB, TB>>>(ei, E, Nn);
    // 6: gather1  (ncu capture target)
    {
        int blocks = (Nn + (TB / 32) - 1) / (TB / 32);
        gather1_kernel<<<blocks, TB>>>(b1, Nn);
    }
    // 7: GEMM2
    h16_gemm_kernel<<<(Nn + 63) / 64, 128>>>(Nn);
    // 8: gather2 -> d_out
    {
        int blocks = (Nn + (TB / 32) - 1) / (TB / 32);
        gather2_kernel<<<blocks, TB>>>(b2, out, Nn);
    }
}